// round 1
// baseline (speedup 1.0000x reference)
#include <cuda_runtime.h>
#include <cuda_bf16.h>
#include <cstdint>

// ---------------- problem constants ----------------
constexpr int NT  = 16384;   // tokens = 8*2048
constexpr int NH  = 2048;    // hidden
constexpr int NE  = 64;      // experts
constexpr int CAP = 512;     // 2*ceil(NT/NE)

constexpr int BM = 64;       // tokens per block
constexpr int BK = 16;       // k tile
constexpr int KT = NH / BK;  // 128 k tiles

// ---------------- device scratch (no allocations allowed) ----------------
__device__ int4               d_tok[NT];            // {top1, top2, p1 bits, p2 bits}
__device__ unsigned long long d_bkt1[NE * NT];      // composite keys, bucketed by top1 expert
__device__ unsigned long long d_bkt2[NE * NT];      // composite keys, bucketed by top2 expert
__device__ int                d_cnt1[NE];
__device__ int                d_cnt2[NE];
__device__ unsigned char      d_keep[2 * NT];       // [0..NT): keep1, [NT..2NT): keep2

// ---------------- packed fp32x2 helpers (sm_100+ PTX) ----------------
__device__ __forceinline__ unsigned long long pk2(float x, float y) {
    unsigned long long r;
    asm("mov.b64 %0, {%1, %2};" : "=l"(r) : "f"(x), "f"(y));
    return r;
}
__device__ __forceinline__ void ffma2(unsigned long long& c,
                                      unsigned long long a,
                                      unsigned long long b) {
    asm("fma.rn.f32x2 %0, %1, %2, %0;" : "+l"(c) : "l"(a), "l"(b));
}
__device__ __forceinline__ void upk2(unsigned long long v, float& lo, float& hi) {
    asm("mov.b64 {%0, %1}, %2;" : "=f"(lo), "=f"(hi) : "l"(v));
}

// ---------------- kernel 0: zero per-expert counters ----------------
__global__ void k_zero_counts() {
    int i = threadIdx.x;
    if (i < NE) { d_cnt1[i] = 0; d_cnt2[i] = 0; }
}

// ---------------- kernel 1: GEMM (fp32, FFMA2) + softmax/top2 epilogue ----------------
// Each block: 64 tokens x all 64 experts, K = 2048.
// Thread tile: 4 tokens x 4 experts, accumulated as 8 f32x2 pairs (expert pairs).
__global__ __launch_bounds__(256, 2) void k_gemm_route(
    const float* __restrict__ X,   // [NT, NH]
    const float* __restrict__ W)   // [NH, NE]
{
    __shared__ float As[2][BK][BM];      // k-major, token contiguous
    __shared__ float Bs[2][BK][NE];      // k-major, expert contiguous
    __shared__ float Cs[BM][NE + 1];     // logits tile (padded stride)

    const int tid = threadIdx.x;
    const int t0  = blockIdx.x * BM;
    const int tx  = tid & 15;            // expert group (x4)
    const int ty  = tid >> 4;            // token group (x4)

    // A tile load mapping: 256 threads x float4 = 64 rows x 16 k
    const int arow = tid >> 2;           // 0..63 (token)
    const int ak   = (tid & 3) << 2;     // 0,4,8,12 (k)
    // B tile load mapping: 16 k rows x 64 experts
    const int brow = tid >> 4;           // 0..15 (k)
    const int bcol = (tid & 15) << 2;    // expert

    const float* Ap = X + (size_t)(t0 + arow) * NH + ak;
    const float* Bp = W + (size_t)brow * NE + bcol;

    unsigned long long acc[4][2];
#pragma unroll
    for (int m = 0; m < 4; ++m) { acc[m][0] = 0ULL; acc[m][1] = 0ULL; }

    // prologue: tile 0
    {
        float4 a = *(const float4*)Ap;
        float4 b = *(const float4*)Bp;
        As[0][ak + 0][arow] = a.x; As[0][ak + 1][arow] = a.y;
        As[0][ak + 2][arow] = a.z; As[0][ak + 3][arow] = a.w;
        *(float4*)&Bs[0][brow][bcol] = b;
    }
    __syncthreads();

    for (int kt = 0; kt < KT; ++kt) {
        const int cur = kt & 1;
        float4 an, bn;
        const bool more = (kt + 1 < KT);
        if (more) {
            an = *(const float4*)(Ap + (size_t)(kt + 1) * BK);
            bn = *(const float4*)(Bp + (size_t)(kt + 1) * BK * NE);
        }
#pragma unroll
        for (int k = 0; k < BK; ++k) {
            const float4 av = *(const float4*)&As[cur][k][ty << 2];
            const ulonglong2 bq = *(const ulonglong2*)&Bs[cur][k][tx << 2];
            const unsigned long long a0 = pk2(av.x, av.x);
            const unsigned long long a1 = pk2(av.y, av.y);
            const unsigned long long a2 = pk2(av.z, av.z);
            const unsigned long long a3 = pk2(av.w, av.w);
            ffma2(acc[0][0], a0, bq.x); ffma2(acc[0][1], a0, bq.y);
            ffma2(acc[1][0], a1, bq.x); ffma2(acc[1][1], a1, bq.y);
            ffma2(acc[2][0], a2, bq.x); ffma2(acc[2][1], a2, bq.y);
            ffma2(acc[3][0], a3, bq.x); ffma2(acc[3][1], a3, bq.y);
        }
        if (more) {
            const int nxt = cur ^ 1;
            As[nxt][ak + 0][arow] = an.x; As[nxt][ak + 1][arow] = an.y;
            As[nxt][ak + 2][arow] = an.z; As[nxt][ak + 3][arow] = an.w;
            *(float4*)&Bs[nxt][brow][bcol] = bn;
        }
        __syncthreads();
    }

    // write accumulators into Cs
#pragma unroll
    for (int m = 0; m < 4; ++m) {
#pragma unroll
        for (int np = 0; np < 2; ++np) {
            float lo, hi;
            upk2(acc[m][np], lo, hi);
            Cs[(ty << 2) + m][(tx << 2) + (np << 1) + 0] = lo;
            Cs[(ty << 2) + m][(tx << 2) + (np << 1) + 1] = hi;
        }
    }
    __syncthreads();

    // per-token epilogue: softmax + top1/top2 + bucket insert
    if (tid < BM) {
        const int t = t0 + tid;
        // top-1 (first index on ties, matching argmax)
        float m0 = Cs[tid][0]; int i1 = 0;
        for (int e = 1; e < NE; ++e) {
            float l = Cs[tid][e];
            if (l > m0) { m0 = l; i1 = e; }
        }
        // top-2: argmax excluding i1 (first index on ties)
        float m2 = -3.402823466e+38f; int i2 = 0;
        for (int e = 0; e < NE; ++e) {
            if (e == i1) continue;
            float l = Cs[tid][e];
            if (l > m2) { m2 = l; i2 = e; }
        }
        float Z = 0.f;
        for (int e = 0; e < NE; ++e) Z += expf(Cs[tid][e] - m0);
        const float p1 = 1.0f / Z;
        const float p2 = expf(m2 - m0) / Z;

        d_tok[t] = make_int4(i1, i2, __float_as_int(p1), __float_as_int(p2));

        // composite sort key: maxprob desc, token idx asc (p1 > 0 so bits are monotone)
        const unsigned long long c =
            ((unsigned long long)__float_as_uint(p1) << 32) |
            (unsigned long long)(0xFFFFFFFFu - (unsigned)t);

        int pos1 = atomicAdd(&d_cnt1[i1], 1);
        d_bkt1[(size_t)i1 * NT + pos1] = c;
        int pos2 = atomicAdd(&d_cnt2[i2], 1);
        d_bkt2[(size_t)i2 * NT + pos2] = c;
    }
}

// ---------------- kernel 2: per-expert capacity ranking ----------------
// blocks 0..63: top-1 buckets; blocks 64..127: top-2 buckets (offset by uncapped cnt1)
__global__ __launch_bounds__(256) void k_rank() {
    __shared__ unsigned long long s[6000];   // 48000 B
    const int bid    = blockIdx.x;
    const int e      = bid & 63;
    const bool second = (bid >= NE);
    const int n      = second ? d_cnt2[e] : d_cnt1[e];
    const unsigned long long* list = (second ? d_bkt2 : d_bkt1) + (size_t)e * NT;
    const int offset = second ? d_cnt1[e] : 0;
    unsigned char* keep = d_keep + (second ? NT : 0);

    if (n <= 6000) {
        for (int i = threadIdx.x; i < n; i += blockDim.x) s[i] = list[i];
        __syncthreads();
        for (int i = threadIdx.x; i < n; i += blockDim.x) {
            const unsigned long long ci = s[i];
            int r = 0;
            for (int j = 0; j < n; ++j) r += (s[j] > ci);
            const int idx = (int)(0xFFFFFFFFu - (unsigned)ci);
            keep[idx] = (unsigned char)((r + offset) < CAP);
        }
    } else {  // safety fallback (not expected with this distribution)
        for (int i = threadIdx.x; i < n; i += blockDim.x) {
            const unsigned long long ci = list[i];
            int r = 0;
            for (int j = 0; j < n; ++j) r += (list[j] > ci);
            const int idx = (int)(0xFFFFFFFFu - (unsigned)ci);
            keep[idx] = (unsigned char)((r + offset) < CAP);
        }
    }
}

// ---------------- kernel 3: finalize outputs ----------------
// out[0 .. NT*NE)          : top_1_mask (after capacity)
// out[NT*NE .. 2*NT*NE)    : gates1 + gates2
__global__ __launch_bounds__(256) void k_finalize(float* __restrict__ out) {
    const int t = blockIdx.x * blockDim.x + threadIdx.x;
    if (t >= NT) return;
    const int4 rec = d_tok[t];
    const float p1 = __int_as_float(rec.z);
    const float p2 = __int_as_float(rec.w);
    const bool k1 = d_keep[t] != 0;
    const bool k2 = d_keep[NT + t] != 0;
    const float p1k = k1 ? p1 : 0.f;
    const float p2k = k2 ? p2 : 0.f;
    const float denom = fmaxf(p1k + p2k, 1.1920929e-07f);
    const float g1 = p1k / denom;
    const float g2 = p2k / denom;

    float* mrow = out + (size_t)t * NE;
    float* prow = out + (size_t)NT * NE + (size_t)t * NE;
    const float4 z = make_float4(0.f, 0.f, 0.f, 0.f);
#pragma unroll
    for (int c = 0; c < NE / 4; ++c) {
        *(float4*)(mrow + (c << 2)) = z;
        *(float4*)(prow + (c << 2)) = z;
    }
    // scalar overwrites after zero-fill (same thread, program order holds)
    mrow[rec.x] = k1 ? 1.0f : 0.0f;
    prow[rec.x] = g1;
    prow[rec.y] = g2;
}

// ---------------- launch ----------------
extern "C" void kernel_launch(void* const* d_in, const int* in_sizes, int n_in,
                              void* d_out, int out_size) {
    (void)in_sizes; (void)n_in; (void)out_size;
    const float* X = (const float*)d_in[0];   // hidden_states  (8,2048,2048)
    const float* W = (const float*)d_in[1];   // classifier_weight (2048,64)
    float* out = (float*)d_out;

    k_zero_counts<<<1, 64>>>();
    k_gemm_route<<<NT / BM, 256>>>(X, W);
    k_rank<<<2 * NE, 256>>>();
    k_finalize<<<NT / 256, 256>>>(out);
}

// round 2
// speedup vs baseline: 1.0002x; 1.0002x over previous
#include <cuda_runtime.h>
#include <cuda_bf16.h>
#include <cstdint>

// ---------------- problem constants ----------------
constexpr int NT  = 16384;   // tokens = 8*2048
constexpr int NH  = 2048;    // hidden
constexpr int NE  = 64;      // experts
constexpr int CAP = 512;     // 2*ceil(NT/NE)

constexpr int BM = 64;       // tokens per block
constexpr int BK = 16;       // k tile
constexpr int KT = NH / BK;  // 128 k tiles

// ---------------- device scratch (no allocations allowed) ----------------
__device__ int4               d_tok[NT];            // {top1, top2, p1 bits, p2 bits}
__device__ unsigned long long d_bkt1[NE * NT];      // composite keys, bucketed by top1 expert
__device__ unsigned long long d_bkt2[NE * NT];      // composite keys, bucketed by top2 expert
__device__ int                d_cnt1[NE];
__device__ int                d_cnt2[NE];
__device__ unsigned char      d_keep[2 * NT];       // [0..NT): keep1, [NT..2NT): keep2

// ---------------- packed fp32x2 helpers (sm_100+ PTX) ----------------
__device__ __forceinline__ unsigned long long pk2(float x, float y) {
    unsigned long long r;
    asm("mov.b64 %0, {%1, %2};" : "=l"(r) : "f"(x), "f"(y));
    return r;
}
__device__ __forceinline__ void ffma2(unsigned long long& c,
                                      unsigned long long a,
                                      unsigned long long b) {
    asm("fma.rn.f32x2 %0, %1, %2, %0;" : "+l"(c) : "l"(a), "l"(b));
}
__device__ __forceinline__ void upk2(unsigned long long v, float& lo, float& hi) {
    asm("mov.b64 {%0, %1}, %2;" : "=f"(lo), "=f"(hi) : "l"(v));
}

// ---------------- kernel 0: zero per-expert counters ----------------
__global__ void k_zero_counts() {
    int i = threadIdx.x;
    if (i < NE) { d_cnt1[i] = 0; d_cnt2[i] = 0; }
}

// ---------------- kernel 1: GEMM (fp32, FFMA2) + softmax/top2 epilogue ----------------
// Each block: 64 tokens x all 64 experts, K = 2048.
// Thread tile: 4 tokens x 4 experts, accumulated as 8 f32x2 pairs (expert pairs).
__global__ __launch_bounds__(256, 2) void k_gemm_route(
    const float* __restrict__ X,   // [NT, NH]
    const float* __restrict__ W)   // [NH, NE]
{
    __shared__ float As[2][BK][BM];      // k-major, token contiguous
    __shared__ float Bs[2][BK][NE];      // k-major, expert contiguous
    __shared__ float Cs[BM][NE + 1];     // logits tile (padded stride)

    const int tid = threadIdx.x;
    const int t0  = blockIdx.x * BM;
    const int tx  = tid & 15;            // expert group (x4)
    const int ty  = tid >> 4;            // token group (x4)

    // A tile load mapping: 256 threads x float4 = 64 rows x 16 k
    const int arow = tid >> 2;           // 0..63 (token)
    const int ak   = (tid & 3) << 2;     // 0,4,8,12 (k)
    // B tile load mapping: 16 k rows x 64 experts
    const int brow = tid >> 4;           // 0..15 (k)
    const int bcol = (tid & 15) << 2;    // expert

    const float* Ap = X + (size_t)(t0 + arow) * NH + ak;
    const float* Bp = W + (size_t)brow * NE + bcol;

    unsigned long long acc[4][2];
#pragma unroll
    for (int m = 0; m < 4; ++m) { acc[m][0] = 0ULL; acc[m][1] = 0ULL; }

    // prologue: tile 0
    {
        float4 a = *(const float4*)Ap;
        float4 b = *(const float4*)Bp;
        As[0][ak + 0][arow] = a.x; As[0][ak + 1][arow] = a.y;
        As[0][ak + 2][arow] = a.z; As[0][ak + 3][arow] = a.w;
        *(float4*)&Bs[0][brow][bcol] = b;
    }
    __syncthreads();

    for (int kt = 0; kt < KT; ++kt) {
        const int cur = kt & 1;
        float4 an, bn;
        const bool more = (kt + 1 < KT);
        if (more) {
            an = *(const float4*)(Ap + (size_t)(kt + 1) * BK);
            bn = *(const float4*)(Bp + (size_t)(kt + 1) * BK * NE);
        }
#pragma unroll
        for (int k = 0; k < BK; ++k) {
            const float4 av = *(const float4*)&As[cur][k][ty << 2];
            const ulonglong2 bq = *(const ulonglong2*)&Bs[cur][k][tx << 2];
            const unsigned long long a0 = pk2(av.x, av.x);
            const unsigned long long a1 = pk2(av.y, av.y);
            const unsigned long long a2 = pk2(av.z, av.z);
            const unsigned long long a3 = pk2(av.w, av.w);
            ffma2(acc[0][0], a0, bq.x); ffma2(acc[0][1], a0, bq.y);
            ffma2(acc[1][0], a1, bq.x); ffma2(acc[1][1], a1, bq.y);
            ffma2(acc[2][0], a2, bq.x); ffma2(acc[2][1], a2, bq.y);
            ffma2(acc[3][0], a3, bq.x); ffma2(acc[3][1], a3, bq.y);
        }
        if (more) {
            const int nxt = cur ^ 1;
            As[nxt][ak + 0][arow] = an.x; As[nxt][ak + 1][arow] = an.y;
            As[nxt][ak + 2][arow] = an.z; As[nxt][ak + 3][arow] = an.w;
            *(float4*)&Bs[nxt][brow][bcol] = bn;
        }
        __syncthreads();
    }

    // write accumulators into Cs
#pragma unroll
    for (int m = 0; m < 4; ++m) {
#pragma unroll
        for (int np = 0; np < 2; ++np) {
            float lo, hi;
            upk2(acc[m][np], lo, hi);
            Cs[(ty << 2) + m][(tx << 2) + (np << 1) + 0] = lo;
            Cs[(ty << 2) + m][(tx << 2) + (np << 1) + 1] = hi;
        }
    }
    __syncthreads();

    // per-token epilogue: softmax + top1/top2 + bucket insert
    if (tid < BM) {
        const int t = t0 + tid;
        // top-1 (first index on ties, matching argmax)
        float m0 = Cs[tid][0]; int i1 = 0;
        for (int e = 1; e < NE; ++e) {
            float l = Cs[tid][e];
            if (l > m0) { m0 = l; i1 = e; }
        }
        // top-2: argmax excluding i1 (first index on ties)
        float m2 = -3.402823466e+38f; int i2 = 0;
        for (int e = 0; e < NE; ++e) {
            if (e == i1) continue;
            float l = Cs[tid][e];
            if (l > m2) { m2 = l; i2 = e; }
        }
        float Z = 0.f;
        for (int e = 0; e < NE; ++e) Z += expf(Cs[tid][e] - m0);
        const float p1 = 1.0f / Z;
        const float p2 = expf(m2 - m0) / Z;

        d_tok[t] = make_int4(i1, i2, __float_as_int(p1), __float_as_int(p2));

        // composite sort key: maxprob desc, token idx asc (p1 > 0 so bits are monotone)
        const unsigned long long c =
            ((unsigned long long)__float_as_uint(p1) << 32) |
            (unsigned long long)(0xFFFFFFFFu - (unsigned)t);

        int pos1 = atomicAdd(&d_cnt1[i1], 1);
        d_bkt1[(size_t)i1 * NT + pos1] = c;
        int pos2 = atomicAdd(&d_cnt2[i2], 1);
        d_bkt2[(size_t)i2 * NT + pos2] = c;
    }
}

// ---------------- kernel 2: per-expert capacity ranking ----------------
// blocks 0..63: top-1 buckets; blocks 64..127: top-2 buckets (offset by uncapped cnt1)
__global__ __launch_bounds__(256) void k_rank() {
    __shared__ unsigned long long s[6000];   // 48000 B
    const int bid    = blockIdx.x;
    const int e      = bid & 63;
    const bool second = (bid >= NE);
    const int n      = second ? d_cnt2[e] : d_cnt1[e];
    const unsigned long long* list = (second ? d_bkt2 : d_bkt1) + (size_t)e * NT;
    const int offset = second ? d_cnt1[e] : 0;
    unsigned char* keep = d_keep + (second ? NT : 0);

    if (n <= 6000) {
        for (int i = threadIdx.x; i < n; i += blockDim.x) s[i] = list[i];
        __syncthreads();
        for (int i = threadIdx.x; i < n; i += blockDim.x) {
            const unsigned long long ci = s[i];
            int r = 0;
            for (int j = 0; j < n; ++j) r += (s[j] > ci);
            const int idx = (int)(0xFFFFFFFFu - (unsigned)ci);
            keep[idx] = (unsigned char)((r + offset) < CAP);
        }
    } else {  // safety fallback (not expected with this distribution)
        for (int i = threadIdx.x; i < n; i += blockDim.x) {
            const unsigned long long ci = list[i];
            int r = 0;
            for (int j = 0; j < n; ++j) r += (list[j] > ci);
            const int idx = (int)(0xFFFFFFFFu - (unsigned)ci);
            keep[idx] = (unsigned char)((r + offset) < CAP);
        }
    }
}

// ---------------- kernel 3: finalize outputs ----------------
// out[0 .. NT*NE)          : top_1_mask (after capacity)
// out[NT*NE .. 2*NT*NE)    : gates1 + gates2
__global__ __launch_bounds__(256) void k_finalize(float* __restrict__ out) {
    const int t = blockIdx.x * blockDim.x + threadIdx.x;
    if (t >= NT) return;
    const int4 rec = d_tok[t];
    const float p1 = __int_as_float(rec.z);
    const float p2 = __int_as_float(rec.w);
    const bool k1 = d_keep[t] != 0;
    const bool k2 = d_keep[NT + t] != 0;
    const float p1k = k1 ? p1 : 0.f;
    const float p2k = k2 ? p2 : 0.f;
    const float denom = fmaxf(p1k + p2k, 1.1920929e-07f);
    const float g1 = p1k / denom;
    const float g2 = p2k / denom;

    float* mrow = out + (size_t)t * NE;
    float* prow = out + (size_t)NT * NE + (size_t)t * NE;
    const float4 z = make_float4(0.f, 0.f, 0.f, 0.f);
#pragma unroll
    for (int c = 0; c < NE / 4; ++c) {
        *(float4*)(mrow + (c << 2)) = z;
        *(float4*)(prow + (c << 2)) = z;
    }
    // scalar overwrites after zero-fill (same thread, program order holds)
    mrow[rec.x] = k1 ? 1.0f : 0.0f;
    prow[rec.x] = g1;
    prow[rec.y] = g2;
}

// ---------------- launch ----------------
extern "C" void kernel_launch(void* const* d_in, const int* in_sizes, int n_in,
                              void* d_out, int out_size) {
    (void)in_sizes; (void)n_in; (void)out_size;
    const float* X = (const float*)d_in[0];   // hidden_states  (8,2048,2048)
    const float* W = (const float*)d_in[1];   // classifier_weight (2048,64)
    float* out = (float*)d_out;

    k_zero_counts<<<1, 64>>>();
    k_gemm_route<<<NT / BM, 256>>>(X, W);
    k_rank<<<2 * NE, 256>>>();
    k_finalize<<<NT / 256, 256>>>(out);
}